// round 14
// baseline (speedup 1.0000x reference)
#include <cuda_runtime.h>

// labels [16, 8, 512, 512] float32
#define HH 512
#define WW 512
#define NIMG 128
#define ROWS 64                       // output rows per band
#define BANDS (HH / ROWS)             // 8
#define NBLOCKS (NIMG * BANDS)        // 1024 CTAs -> single wave at 7 CTAs/SM
#define NTHR 128                      // 4 warps; 4 cols/thread over full 512 width
#define NSTG 4                        // SMEM ring stages (32 KB total)
#define SROWS 4                       // rows per stage
#define TSTAGES ((ROWS + 4 + SROWS - 1) / SROWS)  // 17: rows t=0..67 issued, t<=65 used
#define INV_N (1.0f / 33554432.0f)

__device__ __align__(16) float g_partials[NBLOCKS];
__device__ unsigned int g_counter = 0;

__device__ __forceinline__ void cp16(unsigned sa, const float* g) {
    asm volatile("cp.async.cg.shared.global [%0], [%1], 16;" :: "r"(sa), "l"(g));
}
__device__ __forceinline__ void cpcommit() {
    asm volatile("cp.async.commit_group;" ::: "memory");
}
__device__ __forceinline__ void cpwait() {                 // <= NSTG-2 groups pending
    asm volatile("cp.async.wait_group 2;" ::: "memory");
}

__global__ __launch_bounds__(NTHR) void open_mse_kernel(const float* __restrict__ x,
                                                        float* __restrict__ out) {
    __shared__ float smem[NSTG * SROWS][WW];               // 32 KB
    const int tid  = threadIdx.x;
    const int wid  = tid >> 5;
    const int lane = tid & 31;
    const int band = blockIdx.x & (BANDS - 1);
    const int img  = blockIdx.x >> 3;                      // BANDS = 8
    const int r0   = band * ROWS;
    const bool bottom = (r0 + ROWS == HH);
    const int t_stop  = bottom ? ROWS : (ROWS + 1);        // last erosion-row index t

    const float* base = x + (size_t)img * (HH * WW);
    const int c  = tid * 4;
    const int cL = (c == 0) ? 0 : (c - 1);                 // erosion reflect at col 0
    const int cR = (c + 4 < WW) ? (c + 4) : (WW - 2);      // makes rm[4]=rm[3] at right edge

    // ---- async producer: stage s = rows t in [4s, 4s+3], global row clamp(r0-1+t) ----
    auto issue = [&](int s) {
        #pragma unroll
        for (int k = 0; k < SROWS; ++k) {
            int t = s * SROWS + k;
            int g = r0 - 1 + t;
            g = g < 0 ? 0 : (g > HH - 1 ? HH - 1 : g);
            unsigned sa = (unsigned)__cvta_generic_to_shared(&smem[(s % NSTG) * SROWS + k][c]);
            cp16(sa, base + (size_t)g * WW + c);
        }
        cpcommit();
    };

    #pragma unroll
    for (int s = 0; s < NSTG - 1; ++s) issue(s);           // prefetch stages 0..2

    float rm_prev[5], er_prev[5], x_prev[4];
    float acc = 0.f;

    // fully local per-row update: 4 output cols from a 6-float SMEM window
    auto full_row = [&](const float* row) {
        float4 av = *(const float4*)(row + c);
        float a0 = av.x, a1 = av.y, a2 = av.z, a3 = av.w;
        float xm1 = row[cL], x4r = row[cR];
        float rm[5];
        rm[0] = fminf(xm1, a0); rm[1] = fminf(a0, a1); rm[2] = fminf(a1, a2);
        rm[3] = fminf(a2, a3);  rm[4] = fminf(a3, x4r);
        float er[5], vm[5];
        #pragma unroll
        for (int j = 0; j < 5; ++j) {
            er[j] = fminf(rm_prev[j], rm[j]);
            vm[j] = fmaxf(er_prev[j], er[j]);
        }
        #pragma unroll
        for (int j = 0; j < 4; ++j) {
            float op = fmaxf(vm[j], vm[j + 1]);
            float d  = x_prev[j] - op;
            acc += d * d;
        }
        #pragma unroll
        for (int j = 0; j < 5; ++j) { rm_prev[j] = rm[j]; er_prev[j] = er[j]; }
        x_prev[0] = a0; x_prev[1] = a1; x_prev[2] = a2; x_prev[3] = a3;
    };

    // ---- stage 0: prologue row, first erosion row, two full rows ----
    cpwait();
    __syncthreads();
    issue(NSTG - 1);                                       // stage 3
    {
        // t=0: rowmin of row max(r0-1,0) (reflect at top)
        const float* row = smem[0];
        {
            float4 av = *(const float4*)(row + c);
            float a0 = av.x, a1 = av.y, a2 = av.z, a3 = av.w;
            float xm1 = row[cL], x4r = row[cR];
            rm_prev[0] = fminf(xm1, a0); rm_prev[1] = fminf(a0, a1);
            rm_prev[2] = fminf(a1, a2);  rm_prev[3] = fminf(a2, a3);
            rm_prev[4] = fminf(a3, x4r);
        }
        // t=1: erosion row r0 (no output)
        row = smem[1];
        {
            float4 av = *(const float4*)(row + c);
            float a0 = av.x, a1 = av.y, a2 = av.z, a3 = av.w;
            float xm1 = row[cL], x4r = row[cR];
            float rm[5];
            rm[0] = fminf(xm1, a0); rm[1] = fminf(a0, a1); rm[2] = fminf(a1, a2);
            rm[3] = fminf(a2, a3);  rm[4] = fminf(a3, x4r);
            #pragma unroll
            for (int j = 0; j < 5; ++j) { er_prev[j] = fminf(rm_prev[j], rm[j]); rm_prev[j] = rm[j]; }
            x_prev[0] = a0; x_prev[1] = a1; x_prev[2] = a2; x_prev[3] = a3;
        }
        full_row(smem[2]);                                 // t=2
        full_row(smem[3]);                                 // t=3
    }

    // ---- steady stages 1..16 ----
    for (int s = 1; s < TSTAGES; ++s) {
        cpwait();
        __syncthreads();
        if (s + NSTG - 1 < TSTAGES) issue(s + NSTG - 1); else cpcommit();
        const int sb = (s % NSTG) * SROWS;
        #pragma unroll
        for (int k = 0; k < SROWS; ++k) {
            const int t = s * SROWS + k;
            if (t <= t_stop) full_row(smem[sb + k]);
        }
    }

    // ---- bottom band: emit row H-1 (dilation clamps row 512 -> 511) ----
    if (bottom) {
        #pragma unroll
        for (int j = 0; j < 4; ++j) {
            float op = fmaxf(er_prev[j], er_prev[j + 1]);
            float d  = x_prev[j] - op;
            acc += d * d;
        }
    }

    // ---- block reduction (reuse smem ring as scratch) ----
    #pragma unroll
    for (int o = 16; o > 0; o >>= 1)
        acc += __shfl_xor_sync(0xffffffffu, acc, o);

    __syncthreads();                                       // everyone done reading ring
    float* sm = &smem[0][0];
    if (lane == 0) sm[wid] = acc;
    __syncthreads();
    if (tid == 0) {
        float t = (sm[0] + sm[1]) + (sm[2] + sm[3]);
        g_partials[blockIdx.x] = t;
        __threadfence();
        unsigned int old = atomicAdd(&g_counter, 1u);
        sm[4] = (old == NBLOCKS - 1) ? 1.f : 0.f;
    }
    __syncthreads();

    // ---- last block: deterministic fixed-order final reduction ----
    if (sm[4] != 0.f) {
        const float4* gp4 = (const float4*)g_partials;
        float a = 0.f;
        #pragma unroll
        for (int i = 0; i < NBLOCKS / 4 / NTHR; ++i) {     // 2 iters
            float4 v = gp4[tid + i * NTHR];
            a += (v.x + v.y) + (v.z + v.w);
        }
        #pragma unroll
        for (int o = 16; o > 0; o >>= 1)
            a += __shfl_xor_sync(0xffffffffu, a, o);
        __syncthreads();
        if (lane == 0) sm[8 + wid] = a;
        __syncthreads();
        if (tid == 0) {
            out[0] = ((sm[8] + sm[9]) + (sm[10] + sm[11])) * INV_N;
            g_counter = 0;                                 // self-reset for graph replay
        }
    }
}

extern "C" void kernel_launch(void* const* d_in, const int* in_sizes, int n_in,
                              void* d_out, int out_size) {
    (void)in_sizes; (void)n_in; (void)out_size;
    const float* labels = (const float*)d_in[0];
    float* out = (float*)d_out;
    open_mse_kernel<<<NBLOCKS, NTHR>>>(labels, out);
}

// round 15
// speedup vs baseline: 1.0780x; 1.0780x over previous
#include <cuda_runtime.h>

// labels [16, 8, 512, 512] float32
#define HH 512
#define WW 512
#define NIMG 128
#define ROWS 32                       // output rows per band
#define BANDS (HH / ROWS)             // 16
#define NBLOCKS (NIMG * BANDS)        // 2048 CTAs
#define NTHR 128                      // 4 warps; 4 cols/thread over full 512 width
#define NSTG 4                        // SMEM ring stages (32 KB total) -> 6 CTAs/SM
#define SROWS 4                       // rows per stage
#define TSTAGES 9                     // ceil(36/4): rows t=0..35 issued, t<=33 used
#define INV_N (1.0f / 33554432.0f)

__device__ __align__(16) float g_partials[NBLOCKS];
__device__ unsigned int g_counter = 0;

__device__ __forceinline__ void cp16(unsigned sa, const float* g) {
    asm volatile("cp.async.cg.shared.global [%0], [%1], 16;" :: "r"(sa), "l"(g));
}
__device__ __forceinline__ void cpcommit() {
    asm volatile("cp.async.commit_group;" ::: "memory");
}
__device__ __forceinline__ void cpwait() {                 // <= NSTG-2 groups pending
    asm volatile("cp.async.wait_group 2;" ::: "memory");
}

__global__ __launch_bounds__(NTHR) void open_mse_kernel(const float* __restrict__ x,
                                                        float* __restrict__ out) {
    __shared__ float smem[NSTG * SROWS][WW];               // 32 KB
    const int tid  = threadIdx.x;
    const int wid  = tid >> 5;
    const int lane = tid & 31;
    const int band = blockIdx.x & (BANDS - 1);
    const int img  = blockIdx.x >> 4;                      // BANDS = 16
    const int r0   = band * ROWS;
    const bool bottom = (r0 + ROWS == HH);
    const int t_stop  = bottom ? ROWS : (ROWS + 1);        // last erosion-row index t

    const float* base = x + (size_t)img * (HH * WW);
    const int c  = tid * 4;
    const int cL = (c == 0) ? 0 : (c - 1);                 // erosion reflect at col 0
    const int cR = (c + 4 < WW) ? (c + 4) : (WW - 2);      // makes rm[4]=rm[3] at right edge

    // ---- async producer: stage s = rows t in [4s, 4s+3], global row clamp(r0-1+t) ----
    auto issue = [&](int s) {
        #pragma unroll
        for (int k = 0; k < SROWS; ++k) {
            int t = s * SROWS + k;
            int g = r0 - 1 + t;
            g = g < 0 ? 0 : (g > HH - 1 ? HH - 1 : g);
            unsigned sa = (unsigned)__cvta_generic_to_shared(&smem[(s % NSTG) * SROWS + k][c]);
            cp16(sa, base + (size_t)g * WW + c);
        }
        cpcommit();
    };

    #pragma unroll
    for (int s = 0; s < NSTG - 1; ++s) issue(s);           // prefetch stages 0..2

    float rm_prev[5], er_prev[5], x_prev[4];
    float acc = 0.f;

    // fully local per-row update: 4 output cols from a 6-float SMEM window
    auto full_row = [&](const float* row) {
        float4 av = *(const float4*)(row + c);
        float a0 = av.x, a1 = av.y, a2 = av.z, a3 = av.w;
        float xm1 = row[cL], x4r = row[cR];
        float rm[5];
        rm[0] = fminf(xm1, a0); rm[1] = fminf(a0, a1); rm[2] = fminf(a1, a2);
        rm[3] = fminf(a2, a3);  rm[4] = fminf(a3, x4r);
        float er[5], vm[5];
        #pragma unroll
        for (int j = 0; j < 5; ++j) {
            er[j] = fminf(rm_prev[j], rm[j]);
            vm[j] = fmaxf(er_prev[j], er[j]);
        }
        #pragma unroll
        for (int j = 0; j < 4; ++j) {
            float op = fmaxf(vm[j], vm[j + 1]);
            float d  = x_prev[j] - op;
            acc += d * d;
        }
        #pragma unroll
        for (int j = 0; j < 5; ++j) { rm_prev[j] = rm[j]; er_prev[j] = er[j]; }
        x_prev[0] = a0; x_prev[1] = a1; x_prev[2] = a2; x_prev[3] = a3;
    };

    // ---- stage 0: prologue row, first erosion row, two full rows ----
    cpwait();
    __syncthreads();
    issue(NSTG - 1);                                       // stage 3
    {
        // t=0: rowmin of row max(r0-1,0) (reflect at top)
        const float* row = smem[0];
        {
            float4 av = *(const float4*)(row + c);
            float a0 = av.x, a1 = av.y, a2 = av.z, a3 = av.w;
            float xm1 = row[cL], x4r = row[cR];
            rm_prev[0] = fminf(xm1, a0); rm_prev[1] = fminf(a0, a1);
            rm_prev[2] = fminf(a1, a2);  rm_prev[3] = fminf(a2, a3);
            rm_prev[4] = fminf(a3, x4r);
        }
        // t=1: erosion row r0 (no output)
        row = smem[1];
        {
            float4 av = *(const float4*)(row + c);
            float a0 = av.x, a1 = av.y, a2 = av.z, a3 = av.w;
            float xm1 = row[cL], x4r = row[cR];
            float rm[5];
            rm[0] = fminf(xm1, a0); rm[1] = fminf(a0, a1); rm[2] = fminf(a1, a2);
            rm[3] = fminf(a2, a3);  rm[4] = fminf(a3, x4r);
            #pragma unroll
            for (int j = 0; j < 5; ++j) { er_prev[j] = fminf(rm_prev[j], rm[j]); rm_prev[j] = rm[j]; }
            x_prev[0] = a0; x_prev[1] = a1; x_prev[2] = a2; x_prev[3] = a3;
        }
        full_row(smem[2]);                                 // t=2
        full_row(smem[3]);                                 // t=3
    }

    // ---- steady stages 1..8 ----
    for (int s = 1; s < TSTAGES; ++s) {
        cpwait();
        __syncthreads();
        if (s + NSTG - 1 < TSTAGES) issue(s + NSTG - 1); else cpcommit();
        const int sb = (s % NSTG) * SROWS;
        #pragma unroll
        for (int k = 0; k < SROWS; ++k) {
            const int t = s * SROWS + k;
            if (t <= t_stop) full_row(smem[sb + k]);
        }
    }

    // ---- bottom band: emit row H-1 (dilation clamps row 512 -> 511) ----
    if (bottom) {
        #pragma unroll
        for (int j = 0; j < 4; ++j) {
            float op = fmaxf(er_prev[j], er_prev[j + 1]);
            float d  = x_prev[j] - op;
            acc += d * d;
        }
    }

    // ---- block reduction (reuse smem ring as scratch) ----
    #pragma unroll
    for (int o = 16; o > 0; o >>= 1)
        acc += __shfl_xor_sync(0xffffffffu, acc, o);

    __syncthreads();                                       // everyone done reading ring
    float* sm = &smem[0][0];
    if (lane == 0) sm[wid] = acc;
    __syncthreads();
    if (tid == 0) {
        float t = (sm[0] + sm[1]) + (sm[2] + sm[3]);
        g_partials[blockIdx.x] = t;
        __threadfence();
        unsigned int old = atomicAdd(&g_counter, 1u);
        sm[4] = (old == NBLOCKS - 1) ? 1.f : 0.f;
    }
    __syncthreads();

    // ---- last block: deterministic fixed-order final reduction ----
    if (sm[4] != 0.f) {
        const float4* gp4 = (const float4*)g_partials;
        float a = 0.f;
        #pragma unroll
        for (int i = 0; i < NBLOCKS / 4 / NTHR; ++i) {     // 4 iters
            float4 v = gp4[tid + i * NTHR];
            a += (v.x + v.y) + (v.z + v.w);
        }
        #pragma unroll
        for (int o = 16; o > 0; o >>= 1)
            a += __shfl_xor_sync(0xffffffffu, a, o);
        __syncthreads();
        if (lane == 0) sm[8 + wid] = a;
        __syncthreads();
        if (tid == 0) {
            out[0] = ((sm[8] + sm[9]) + (sm[10] + sm[11])) * INV_N;
            g_counter = 0;                                 // self-reset for graph replay
        }
    }
}

extern "C" void kernel_launch(void* const* d_in, const int* in_sizes, int n_in,
                              void* d_out, int out_size) {
    (void)in_sizes; (void)n_in; (void)out_size;
    const float* labels = (const float*)d_in[0];
    float* out = (float*)d_out;
    open_mse_kernel<<<NBLOCKS, NTHR>>>(labels, out);
}